// round 16
// baseline (speedup 1.0000x reference)
#include <cuda_runtime.h>
#include <cuda_bf16.h>
#include <cuda_fp16.h>
#include <math.h>
#include <stdint.h>

// Problem constants
#define Bb   4
#define Tt   1024
#define DIM  2048
#define Hh   16
#define KVH  4
#define Gg   4
#define HD   128

#define MROWS (Bb * Tt)          // 4096
#define NKV   (2 * KVH * HD)     // 1024
#define NQKV  (DIM + NKV)        // 3072 (merged q|kv output width)

// fp16 scratch
__device__ __align__(256) __half g_xs   [MROWS * DIM];
__device__ __align__(256) __half g_ctxs [MROWS * DIM];
__device__ __align__(256) __half g_qkv16[MROWS * NQKV];   // GEMM output (fp16)
__device__ __align__(256) __half g_wqkv [DIM * NQKV];     // [Wq | Wkv]
__device__ __align__(256) __half g_wos  [DIM * DIM];

// fp16 attention operands (rope + scale applied), head-major:
__device__ __align__(256) __half g_qs16[Bb * Hh * Tt * HD];
__device__ __align__(256) __half g_ks16[Bb * KVH * Tt * HD];
__device__ __align__(256) __half g_vs16[Bb * KVH * Tt * HD];

// ---------------------------------------------------------------------------
// PTX helpers
// ---------------------------------------------------------------------------
__device__ __forceinline__ void ldsm_x4(uint32_t& r0, uint32_t& r1,
                                        uint32_t& r2, uint32_t& r3, uint32_t addr) {
    asm volatile("ldmatrix.sync.aligned.m8n8.x4.shared.b16 {%0,%1,%2,%3}, [%4];\n"
                 : "=r"(r0), "=r"(r1), "=r"(r2), "=r"(r3) : "r"(addr));
}
__device__ __forceinline__ void ldsm_x4_t(uint32_t& r0, uint32_t& r1,
                                          uint32_t& r2, uint32_t& r3, uint32_t addr) {
    asm volatile("ldmatrix.sync.aligned.m8n8.x4.trans.shared.b16 {%0,%1,%2,%3}, [%4];\n"
                 : "=r"(r0), "=r"(r1), "=r"(r2), "=r"(r3) : "r"(addr));
}
__device__ __forceinline__ void mma_f16(float* c, const uint32_t* a,
                                        uint32_t b0, uint32_t b1) {
    asm volatile(
        "mma.sync.aligned.m16n8k16.row.col.f32.f16.f16.f32 "
        "{%0,%1,%2,%3}, {%4,%5,%6,%7}, {%8,%9}, {%0,%1,%2,%3};\n"
        : "+f"(c[0]), "+f"(c[1]), "+f"(c[2]), "+f"(c[3])
        : "r"(a[0]), "r"(a[1]), "r"(a[2]), "r"(a[3]), "r"(b0), "r"(b1));
}
#define CP_ASYNC16(dst, src) \
    asm volatile("cp.async.cg.shared.global [%0], [%1], 16;\n" :: "r"(dst), "l"(src))
#define CP_COMMIT() asm volatile("cp.async.commit_group;\n" ::: "memory")
template <int N>
__device__ __forceinline__ void cp_wait() {
    asm volatile("cp.async.wait_group %0;\n" :: "n"(N) : "memory");
}

// ---------------------------------------------------------------------------
// Conversion kernels
// ---------------------------------------------------------------------------
__global__ void conv_h(const float* __restrict__ in,
                       __half* __restrict__ out, int n) {
    int idx = blockIdx.x * blockDim.x + threadIdx.x;
    int i4 = idx * 4;
    if (i4 >= n) return;
    float4 v = *(const float4*)&in[i4];
    *(__half2*)&out[i4]     = __floats2half2_rn(v.x, v.y);
    *(__half2*)&out[i4 + 2] = __floats2half2_rn(v.z, v.w);
}
// Fill g_wqkv = [Wq | Wkv] (fp16), row k has 3072 cols
__global__ void conv_wqkv(const float* __restrict__ Wq,
                          const float* __restrict__ Wkv,
                          __half* __restrict__ out) {
    int idx = blockIdx.x * blockDim.x + threadIdx.x;
    int i4 = idx * 4;
    if (i4 >= DIM * NQKV) return;
    int k = i4 / NQKV, col = i4 - k * NQKV;   // col aligned to 4
    float4 v;
    if (col < DIM) v = *(const float4*)&Wq[(size_t)k * DIM + col];
    else           v = *(const float4*)&Wkv[(size_t)k * NKV + (col - DIM)];
    *(__half2*)&out[i4]     = __floats2half2_rn(v.x, v.y);
    *(__half2*)&out[i4 + 2] = __floats2half2_rn(v.z, v.w);
}

// ---------------------------------------------------------------------------
// fp16 TC GEMM: C[M,N] = A[M,K] h @ B[K,N] h, OutT in {float, __half}
// 128x256 CTA tile, BK=32, 4-stage cp.async (wait_group 2), 8 warps 64x64.
// ---------------------------------------------------------------------------
#define LDA 40    // halfs per A smem row (32 + 8)
#define LDB 264   // halfs per B smem row (256 + 8)
#define GSTAGES 4
#define G_ASZ (128 * LDA * 2)
#define G_BSZ (32 * LDB * 2)
#define G_STG (G_ASZ + G_BSZ)
#define GEMM_SMEM (GSTAGES * G_STG)

template <typename OutT>
__global__ __launch_bounds__(256, 1) void hgemm256(const __half* __restrict__ A,
                                                   const __half* __restrict__ B,
                                                   OutT* __restrict__ C,
                                                   int M, int N, int K) {
    extern __shared__ __half gsm[];

    const int tid  = threadIdx.x;
    const int lane = tid & 31;
    const int w    = tid >> 5;
    const int wm   = (w & 1) * 64;
    const int wn   = (w >> 1) * 64;
    const int rowBase = blockIdx.y * 128;
    const int colBase = blockIdx.x * 256;

    const uint32_t S0 = (uint32_t)__cvta_generic_to_shared(gsm);

    float acc[4][8][4];
#pragma unroll
    for (int mi = 0; mi < 4; mi++)
#pragma unroll
        for (int ni = 0; ni < 8; ni++)
#pragma unroll
            for (int r = 0; r < 4; r++) acc[mi][ni][r] = 0.0f;

    const int NI = K / 32;

    auto load_stage = [&](int it, int s) {
        int k0 = it * 32;
        const uint32_t aB = S0 + s * G_STG;
        const uint32_t bB = aB + G_ASZ;
#pragma unroll
        for (int c = 0; c < 2; c++) {               // A: 512 chunks of 16B
            int i = tid + c * 256;
            int row = i >> 2, cc = (i & 3) * 8;
            const __half* src = A + (size_t)(rowBase + row) * K + k0 + cc;
            CP_ASYNC16(aB + (row * LDA + cc) * 2, src);
        }
#pragma unroll
        for (int c = 0; c < 4; c++) {               // B: 1024 chunks
            int i = tid + c * 256;
            int row = i >> 5, cc = (i & 31) * 8;
            const __half* src = B + (size_t)(k0 + row) * N + colBase + cc;
            CP_ASYNC16(bB + (row * LDB + cc) * 2, src);
        }
        CP_COMMIT();
    };

    load_stage(0, 0);
    load_stage(1, 1);
    load_stage(2, 2);

    for (int it = 0; it < NI; ++it) {
        cp_wait<2>();
        __syncthreads();
        if (it + 3 < NI) load_stage(it + 3, (it + 3) & 3);
        else CP_COMMIT();

        const int s = it & 3;
        const uint32_t aB = S0 + s * G_STG;
        const uint32_t bB = aB + G_ASZ;

#pragma unroll
        for (int ks = 0; ks < 32; ks += 16) {
            uint32_t ra[4][4], rb[4][4];
#pragma unroll
            for (int mi = 0; mi < 4; mi++) {
                uint32_t addr = aB +
                    ((wm + mi * 16 + (lane & 15)) * LDA + ks + (lane >> 4) * 8) * 2;
                ldsm_x4(ra[mi][0], ra[mi][1], ra[mi][2], ra[mi][3], addr);
            }
#pragma unroll
            for (int g = 0; g < 4; g++) {
                uint32_t addr = bB +
                    ((ks + (lane & 15)) * LDB + wn + g * 16 + (lane >> 4) * 8) * 2;
                ldsm_x4_t(rb[g][0], rb[g][1], rb[g][2], rb[g][3], addr);
            }
#pragma unroll
            for (int mi = 0; mi < 4; mi++)
#pragma unroll
                for (int ni = 0; ni < 8; ni++)
                    mma_f16(acc[mi][ni], ra[mi],
                            rb[ni >> 1][(ni & 1) * 2], rb[ni >> 1][(ni & 1) * 2 + 1]);
        }
    }

#pragma unroll
    for (int mi = 0; mi < 4; mi++)
#pragma unroll
        for (int ni = 0; ni < 8; ni++) {
            int r = rowBase + wm + mi * 16 + (lane >> 2);
            int cc = colBase + wn + ni * 8 + (lane & 3) * 2;
            if constexpr (sizeof(OutT) == 4) {
                *(float2*)&C[(size_t)r * N + cc] =
                    make_float2(acc[mi][ni][0], acc[mi][ni][1]);
                *(float2*)&C[(size_t)(r + 8) * N + cc] =
                    make_float2(acc[mi][ni][2], acc[mi][ni][3]);
            } else {
                *(__half2*)&C[(size_t)r * N + cc] =
                    __floats2half2_rn(acc[mi][ni][0], acc[mi][ni][1]);
                *(__half2*)&C[(size_t)(r + 8) * N + cc] =
                    __floats2half2_rn(acc[mi][ni][2], acc[mi][ni][3]);
            }
        }
}

// ---------------------------------------------------------------------------
// Fused prep: RoPE + scale + head-major relayout, fp16 in / fp16 out.
// qkv layout: [M, 3072] = [q(2048) | k(512) | v(512)]
// ---------------------------------------------------------------------------
__global__ void prep_kernel(const __half* __restrict__ qkv,
                            const float* __restrict__ cosb,
                            const float* __restrict__ sinb,
                            __half* __restrict__ qs,
                            __half* __restrict__ ks,
                            __half* __restrict__ vs) {
    const int NQ = Bb * Tt * Hh * 64;
    const int NK = Bb * Tt * KVH * 64;
    const int NV = Bb * Tt * KVH * 128;
    const float scale = 0.08838834764831845f;
    int idx = blockIdx.x * blockDim.x + threadIdx.x;
    if (idx < NQ) {
        int d = idx & 63;
        int h = (idx >> 6) & 15;
        int t = (idx >> 10) & 1023;
        int b = idx >> 20;
        float c = cosb[t * 64 + d];
        float s = sinb[t * 64 + d];
        size_t src = (size_t)(b * Tt + t) * NQKV + h * HD;
        float u1 = __half2float(qkv[src + d]);
        float u2 = __half2float(qkv[src + 64 + d]);
        size_t dst = ((size_t)(b * Hh + h) * Tt + t) * HD;
        qs[dst + d]      = __float2half((u1 * c - u2 * s) * scale);
        qs[dst + 64 + d] = __float2half((u1 * s + u2 * c) * scale);
    } else if (idx < NQ + NK) {
        int j = idx - NQ;
        int d = j & 63;
        int kvh = (j >> 6) & 3;
        int t = (j >> 8) & 1023;
        int b = j >> 18;
        float c = cosb[t * 64 + d];
        float s = sinb[t * 64 + d];
        size_t src = (size_t)(b * Tt + t) * NQKV + DIM + kvh * HD;
        float u1 = __half2float(qkv[src + d]);
        float u2 = __half2float(qkv[src + 64 + d]);
        size_t dst = ((size_t)(b * KVH + kvh) * Tt + t) * HD;
        ks[dst + d]      = __float2half(u1 * c - u2 * s);
        ks[dst + 64 + d] = __float2half(u1 * s + u2 * c);
    } else if (idx < NQ + NK + NV) {
        int j = idx - NQ - NK;
        int d = j & 127;
        int kvh = (j >> 7) & 3;
        int t = (j >> 9) & 1023;
        int b = j >> 19;
        size_t src = (size_t)(b * Tt + t) * NQKV + DIM + KVH * HD + kvh * HD + d;
        size_t dst = ((size_t)(b * KVH + kvh) * Tt + t) * HD;
        vs[dst + d] = qkv[src];
    }
}

// ---------------------------------------------------------------------------
// Tensor-core flash attention, plain fp16, cp.async double-buffered K/V.
// CTA: 64 q rows of one (b,h). 128 threads = 4 warps.
// ---------------------------------------------------------------------------
#define LDH2 136                      // halfs per row (128 + 8 pad)
#define F2_TILE (64 * LDH2 * 2)       // bytes per 64-row tile
#define FLASH_SMEM (5 * F2_TILE)      // Q + 2xK + 2xV  (~87 KB)

__global__ __launch_bounds__(128) void flash_tc(const __half* __restrict__ qs,
                                                const __half* __restrict__ ks,
                                                const __half* __restrict__ vs,
                                                __half* __restrict__ ctxs) {
    extern __shared__ __half fsm[];

    const int qtile = blockIdx.x;
    const int h     = blockIdx.y;
    const int b     = blockIdx.z;
    const int kvh   = h >> 2;
    const int qbase = qtile * 64;

    const int tid  = threadIdx.x;
    const int lane = tid & 31;
    const int w    = tid >> 5;
    const int gid  = lane >> 2;
    const int tig  = lane & 3;

    const uint32_t QsA = (uint32_t)__cvta_generic_to_shared(fsm);
    const uint32_t KsA = QsA + F2_TILE;
    const uint32_t VsA = KsA + 2 * F2_TILE;

    {
        const __half* qsrc = qs + ((size_t)(b * Hh + h) * Tt + qbase) * HD;
#pragma unroll
        for (int i = 0; i < 8; i++) {
            int c = tid + i * 128;
            int r = c >> 4, cc = (c & 15) * 8;
            CP_ASYNC16(QsA + (r * LDH2 + cc) * 2, qsrc + r * HD + cc);
        }
        CP_COMMIT();
    }

    auto load_kv = [&](int kt, int s) {
        const __half* kb = ks + ((size_t)(b * KVH + kvh) * Tt + kt * 64) * HD;
        const __half* vb = vs + ((size_t)(b * KVH + kvh) * Tt + kt * 64) * HD;
        const uint32_t kd = KsA + s * F2_TILE;
        const uint32_t vd = VsA + s * F2_TILE;
#pragma unroll
        for (int i = 0; i < 8; i++) {
            int c = tid + i * 128;
            int r = c >> 4, cc = (c & 15) * 8;
            CP_ASYNC16(kd + (r * LDH2 + cc) * 2, kb + r * HD + cc);
        }
#pragma unroll
        for (int i = 0; i < 8; i++) {
            int c = tid + i * 128;
            int r = c >> 4, cc = (c & 15) * 8;
            CP_ASYNC16(vd + (r * LDH2 + cc) * 2, vb + r * HD + cc);
        }
        CP_COMMIT();
    };

    load_kv(0, 0);

    float oacc[16][4];
#pragma unroll
    for (int t = 0; t < 16; t++)
#pragma unroll
        for (int r = 0; r < 4; r++) oacc[t][r] = 0.0f;
    float m0 = -INFINITY, m1 = -INFINITY, l0 = 0.0f, l1 = 0.0f;

    for (int kt = 0; kt <= qtile; ++kt) {
        if (kt < qtile) load_kv(kt + 1, (kt + 1) & 1);
        else CP_COMMIT();
        cp_wait<1>();
        __syncthreads();

        const uint32_t kB = KsA + (kt & 1) * F2_TILE;
        const uint32_t vB = VsA + (kt & 1) * F2_TILE;

        float sacc[8][4];
#pragma unroll
        for (int t = 0; t < 8; t++)
#pragma unroll
            for (int r = 0; r < 4; r++) sacc[t][r] = 0.0f;

#pragma unroll
        for (int kc = 0; kc < 8; kc++) {
            uint32_t qf[4];
            uint32_t aaddr = QsA +
                ((w * 16 + (lane & 15)) * LDH2 + kc * 16 + (lane >> 4) * 8) * 2;
            ldsm_x4(qf[0], qf[1], qf[2], qf[3], aaddr);
#pragma unroll
            for (int g = 0; g < 4; g++) {
                uint32_t kf[4];
                uint32_t baddr = kB +
                    ((g * 16 + (lane & 15)) * LDH2 + kc * 16 + (lane >> 4) * 8) * 2;
                ldsm_x4(kf[0], kf[1], kf[2], kf[3], baddr);
                mma_f16(sacc[2 * g],     qf, kf[0], kf[2]);
                mma_f16(sacc[2 * g + 1], qf, kf[1], kf[3]);
            }
        }

        if (kt == qtile) {
            int row0 = w * 16 + gid;
#pragma unroll
            for (int s8 = 0; s8 < 8; s8++) {
                int cb = s8 * 8 + tig * 2;
                if (cb     > row0)     sacc[s8][0] = -INFINITY;
                if (cb + 1 > row0)     sacc[s8][1] = -INFINITY;
                if (cb     > row0 + 8) sacc[s8][2] = -INFINITY;
                if (cb + 1 > row0 + 8) sacc[s8][3] = -INFINITY;
            }
        }

        float mx0 = -INFINITY, mx1 = -INFINITY;
#pragma unroll
        for (int s8 = 0; s8 < 8; s8++) {
            mx0 = fmaxf(mx0, fmaxf(sacc[s8][0], sacc[s8][1]));
            mx1 = fmaxf(mx1, fmaxf(sacc[s8][2], sacc[s8][3]));
        }
#pragma unroll
        for (int o = 1; o < 4; o <<= 1) {
            mx0 = fmaxf(mx0, __shfl_xor_sync(0xffffffffu, mx0, o));
            mx1 = fmaxf(mx1, __shfl_xor_sync(0xffffffffu, mx1, o));
        }
        float mn0 = fmaxf(m0, mx0), mn1 = fmaxf(m1, mx1);
        float f0 = __expf(m0 - mn0), f1 = __expf(m1 - mn1);
        float rs0 = 0.0f, rs1 = 0.0f;
#pragma unroll
        for (int s8 = 0; s8 < 8; s8++) {
            sacc[s8][0] = __expf(sacc[s8][0] - mn0);
            sacc[s8][1] = __expf(sacc[s8][1] - mn0);
            sacc[s8][2] = __expf(sacc[s8][2] - mn1);
            sacc[s8][3] = __expf(sacc[s8][3] - mn1);
            rs0 += sacc[s8][0] + sacc[s8][1];
            rs1 += sacc[s8][2] + sacc[s8][3];
        }
#pragma unroll
        for (int o = 1; o < 4; o <<= 1) {
            rs0 += __shfl_xor_sync(0xffffffffu, rs0, o);
            rs1 += __shfl_xor_sync(0xffffffffu, rs1, o);
        }
        l0 = l0 * f0 + rs0; m0 = mn0;
        l1 = l1 * f1 + rs1; m1 = mn1;
#pragma unroll
        for (int t = 0; t < 16; t++) {
            oacc[t][0] *= f0; oacc[t][1] *= f0;
            oacc[t][2] *= f1; oacc[t][3] *= f1;
        }

        uint32_t aP[4][4];
#pragma unroll
        for (int j = 0; j < 4; j++) {
#pragma unroll
            for (int half = 0; half < 2; half++) {
                int t = 2 * j + half;
                __half2 p01 = __floats2half2_rn(sacc[t][0], sacc[t][1]);
                __half2 p23 = __floats2half2_rn(sacc[t][2], sacc[t][3]);
                aP[j][2 * half]     = *(uint32_t*)&p01;
                aP[j][2 * half + 1] = *(uint32_t*)&p23;
            }
        }

#pragma unroll
        for (int j = 0; j < 4; j++) {
#pragma unroll
            for (int g = 0; g < 8; g++) {
                uint32_t vf[4];
                uint32_t baddr = vB +
                    ((j * 16 + (lane & 15)) * LDH2 + g * 16 + (lane >> 4) * 8) * 2;
                ldsm_x4_t(vf[0], vf[1], vf[2], vf[3], baddr);
                mma_f16(oacc[2 * g],     aP[j], vf[0], vf[1]);
                mma_f16(oacc[2 * g + 1], aP[j], vf[2], vf[3]);
            }
        }
        __syncthreads();
    }

    float inv0 = 1.0f / l0, inv1 = 1.0f / l1;
    int r0g = qbase + w * 16 + gid;
    size_t m0r = (size_t)(b * Tt + r0g) * DIM;
    size_t m1r = (size_t)(b * Tt + r0g + 8) * DIM;
#pragma unroll
    for (int t = 0; t < 16; t++) {
        int col = h * HD + t * 8 + tig * 2;
        *(__half2*)&ctxs[m0r + col] =
            __floats2half2_rn(oacc[t][0] * inv0, oacc[t][1] * inv0);
        *(__half2*)&ctxs[m1r + col] =
            __floats2half2_rn(oacc[t][2] * inv1, oacc[t][3] * inv1);
    }
}

// ---------------------------------------------------------------------------
// Launch
// ---------------------------------------------------------------------------
extern "C" void kernel_launch(void* const* d_in, const int* in_sizes, int n_in,
                              void* d_out, int out_size) {
    const float* x    = (const float*)d_in[0];
    const float* Wq   = (const float*)d_in[1];
    const float* Wkv  = (const float*)d_in[2];
    const float* Wo   = (const float*)d_in[3];
    const float* cosb = (const float*)d_in[4];
    const float* sinb = (const float*)d_in[5];
    float* out = (float*)d_out;

    __half *xs, *ctxs, *qkv16, *wqkv, *wos, *qsb, *ksb, *vsb;
    cudaGetSymbolAddress((void**)&xs,     g_xs);
    cudaGetSymbolAddress((void**)&ctxs,   g_ctxs);
    cudaGetSymbolAddress((void**)&qkv16,  g_qkv16);
    cudaGetSymbolAddress((void**)&wqkv,   g_wqkv);
    cudaGetSymbolAddress((void**)&wos,    g_wos);
    cudaGetSymbolAddress((void**)&qsb,    g_qs16);
    cudaGetSymbolAddress((void**)&ksb,    g_ks16);
    cudaGetSymbolAddress((void**)&vsb,    g_vs16);

    cudaFuncSetAttribute(hgemm256<__half>, cudaFuncAttributeMaxDynamicSharedMemorySize,
                         GEMM_SMEM);
    cudaFuncSetAttribute(hgemm256<float>, cudaFuncAttributeMaxDynamicSharedMemorySize,
                         GEMM_SMEM);
    cudaFuncSetAttribute(flash_tc, cudaFuncAttributeMaxDynamicSharedMemorySize,
                         FLASH_SMEM);

    const int M = MROWS;  // 4096

    // Conversions
    conv_h<<<(M * DIM / 4 + 255) / 256, 256>>>(x, xs, M * DIM);
    conv_wqkv<<<(DIM * NQKV / 4 + 255) / 256, 256>>>(Wq, Wkv, wqkv);
    conv_h<<<(DIM * DIM / 4 + 255) / 256, 256>>>(Wo, wos, DIM * DIM);

    // [q | kv] = x @ [Wq | Wkv]  (one merged GEMM, fp16 out)
    hgemm256<__half><<<dim3(NQKV / 256, M / 128), 256, GEMM_SMEM>>>(
        xs, wqkv, qkv16, M, NQKV, DIM);

    // fused rope + fp16 relayout
    {
        int total = Bb * Tt * Hh * 64 + Bb * Tt * KVH * 64 + Bb * Tt * KVH * 128;
        prep_kernel<<<(total + 255) / 256, 256>>>(qkv16, cosb, sinb, qsb, ksb, vsb);
    }

    // attention (fp16 single-term) -> fp16 ctx
    flash_tc<<<dim3(Tt / 64, Hh, Bb), 128, FLASH_SMEM>>>(qsb, ksb, vsb, ctxs);

    // out = ctx @ Wo (fp32 out)
    hgemm256<float><<<dim3(DIM / 256, M / 128), 256, GEMM_SMEM>>>(
        ctxs, wos, out, M, DIM, DIM);
}

// round 17
// speedup vs baseline: 1.0992x; 1.0992x over previous
#include <cuda_runtime.h>
#include <cuda_bf16.h>
#include <cuda_fp16.h>
#include <math.h>
#include <stdint.h>

// Problem constants
#define Bb   4
#define Tt   1024
#define DIM  2048
#define Hh   16
#define KVH  4
#define Gg   4
#define HD   128

#define MROWS (Bb * Tt)          // 4096
#define NKV   (2 * KVH * HD)     // 1024
#define NQKV  (DIM + NKV)        // 3072 (merged q|kv output width)

// fp16 scratch
__device__ __align__(256) __half g_xs   [MROWS * DIM];
__device__ __align__(256) __half g_ctxs [MROWS * DIM];
__device__ __align__(256) __half g_qkv16[MROWS * NQKV];   // GEMM output (fp16)
__device__ __align__(256) __half g_wqkv [DIM * NQKV];     // [Wq | Wkv]
__device__ __align__(256) __half g_wos  [DIM * DIM];

// fp16 attention operands (rope + scale applied), head-major:
__device__ __align__(256) __half g_qs16[Bb * Hh * Tt * HD];
__device__ __align__(256) __half g_ks16[Bb * KVH * Tt * HD];
__device__ __align__(256) __half g_vs16[Bb * KVH * Tt * HD];

// ---------------------------------------------------------------------------
// PTX helpers
// ---------------------------------------------------------------------------
__device__ __forceinline__ void ldsm_x4(uint32_t& r0, uint32_t& r1,
                                        uint32_t& r2, uint32_t& r3, uint32_t addr) {
    asm volatile("ldmatrix.sync.aligned.m8n8.x4.shared.b16 {%0,%1,%2,%3}, [%4];\n"
                 : "=r"(r0), "=r"(r1), "=r"(r2), "=r"(r3) : "r"(addr));
}
__device__ __forceinline__ void ldsm_x4_t(uint32_t& r0, uint32_t& r1,
                                          uint32_t& r2, uint32_t& r3, uint32_t addr) {
    asm volatile("ldmatrix.sync.aligned.m8n8.x4.trans.shared.b16 {%0,%1,%2,%3}, [%4];\n"
                 : "=r"(r0), "=r"(r1), "=r"(r2), "=r"(r3) : "r"(addr));
}
__device__ __forceinline__ void mma_f16(float* c, const uint32_t* a,
                                        uint32_t b0, uint32_t b1) {
    asm volatile(
        "mma.sync.aligned.m16n8k16.row.col.f32.f16.f16.f32 "
        "{%0,%1,%2,%3}, {%4,%5,%6,%7}, {%8,%9}, {%0,%1,%2,%3};\n"
        : "+f"(c[0]), "+f"(c[1]), "+f"(c[2]), "+f"(c[3])
        : "r"(a[0]), "r"(a[1]), "r"(a[2]), "r"(a[3]), "r"(b0), "r"(b1));
}
#define CP_ASYNC16(dst, src) \
    asm volatile("cp.async.cg.shared.global [%0], [%1], 16;\n" :: "r"(dst), "l"(src))
#define CP_COMMIT() asm volatile("cp.async.commit_group;\n" ::: "memory")
template <int N>
__device__ __forceinline__ void cp_wait() {
    asm volatile("cp.async.wait_group %0;\n" :: "n"(N) : "memory");
}

// ---------------------------------------------------------------------------
// Conversion kernels
// ---------------------------------------------------------------------------
__global__ void conv_h(const float* __restrict__ in,
                       __half* __restrict__ out, int n) {
    int idx = blockIdx.x * blockDim.x + threadIdx.x;
    int i4 = idx * 4;
    if (i4 >= n) return;
    float4 v = *(const float4*)&in[i4];
    *(__half2*)&out[i4]     = __floats2half2_rn(v.x, v.y);
    *(__half2*)&out[i4 + 2] = __floats2half2_rn(v.z, v.w);
}
// Fill g_wqkv = [Wq | Wkv] (fp16), row k has 3072 cols
__global__ void conv_wqkv(const float* __restrict__ Wq,
                          const float* __restrict__ Wkv,
                          __half* __restrict__ out) {
    int idx = blockIdx.x * blockDim.x + threadIdx.x;
    int i4 = idx * 4;
    if (i4 >= DIM * NQKV) return;
    int k = i4 / NQKV, col = i4 - k * NQKV;   // col aligned to 4
    float4 v;
    if (col < DIM) v = *(const float4*)&Wq[(size_t)k * DIM + col];
    else           v = *(const float4*)&Wkv[(size_t)k * NKV + (col - DIM)];
    *(__half2*)&out[i4]     = __floats2half2_rn(v.x, v.y);
    *(__half2*)&out[i4 + 2] = __floats2half2_rn(v.z, v.w);
}

// ---------------------------------------------------------------------------
// fp16 TC GEMM: C[M,N] = A[M,K] h @ B[K,N] h, OutT in {float, __half}
// 128x128 CTA tile, BK=32, 4-stage cp.async (wait_group 2), 256 threads,
// 8 warps as 2(m) x 4(n) of 64x32 warp tiles. 2 CTAs/SM for latency hiding.
// ---------------------------------------------------------------------------
#define LDA 40     // halfs per A smem row (32 + 8)
#define LDB2 136   // halfs per B smem row (128 + 8)
#define GSTAGES 4
#define G_ASZ (128 * LDA * 2)     // 10240 B
#define G_BSZ (32 * LDB2 * 2)     // 8704 B
#define G_STG (G_ASZ + G_BSZ)     // 18944 B
#define GEMM_SMEM (GSTAGES * G_STG)   // 75776 B

template <typename OutT>
__global__ __launch_bounds__(256, 2) void hgemm128(const __half* __restrict__ A,
                                                   const __half* __restrict__ B,
                                                   OutT* __restrict__ C,
                                                   int M, int N, int K) {
    extern __shared__ __half gsm[];

    const int tid  = threadIdx.x;
    const int lane = tid & 31;
    const int w    = tid >> 5;
    const int wm   = (w & 1) * 64;      // 2 warp rows
    const int wn   = (w >> 1) * 32;     // 4 warp cols
    const int rowBase = blockIdx.y * 128;
    const int colBase = blockIdx.x * 128;

    const uint32_t S0 = (uint32_t)__cvta_generic_to_shared(gsm);

    float acc[4][4][4];
#pragma unroll
    for (int mi = 0; mi < 4; mi++)
#pragma unroll
        for (int ni = 0; ni < 4; ni++)
#pragma unroll
            for (int r = 0; r < 4; r++) acc[mi][ni][r] = 0.0f;

    const int NI = K / 32;

    auto load_stage = [&](int it, int s) {
        int k0 = it * 32;
        const uint32_t aB = S0 + s * G_STG;
        const uint32_t bB = aB + G_ASZ;
        // A: 128 rows x 4 chunks = 512 chunks, 2/thread
#pragma unroll
        for (int c = 0; c < 2; c++) {
            int i = tid + c * 256;
            int row = i >> 2, cc = (i & 3) * 8;
            const __half* src = A + (size_t)(rowBase + row) * K + k0 + cc;
            CP_ASYNC16(aB + (row * LDA + cc) * 2, src);
        }
        // B: 32 rows x 16 chunks = 512 chunks, 2/thread
#pragma unroll
        for (int c = 0; c < 2; c++) {
            int i = tid + c * 256;
            int row = i >> 4, cc = (i & 15) * 8;
            const __half* src = B + (size_t)(k0 + row) * N + colBase + cc;
            CP_ASYNC16(bB + (row * LDB2 + cc) * 2, src);
        }
        CP_COMMIT();
    };

    load_stage(0, 0);
    load_stage(1, 1);
    load_stage(2, 2);

    for (int it = 0; it < NI; ++it) {
        cp_wait<2>();
        __syncthreads();
        if (it + 3 < NI) load_stage(it + 3, (it + 3) & 3);
        else CP_COMMIT();

        const int s = it & 3;
        const uint32_t aB = S0 + s * G_STG;
        const uint32_t bB = aB + G_ASZ;

#pragma unroll
        for (int ks = 0; ks < 32; ks += 16) {
            uint32_t ra[4][4], rb[2][4];
#pragma unroll
            for (int mi = 0; mi < 4; mi++) {
                uint32_t addr = aB +
                    ((wm + mi * 16 + (lane & 15)) * LDA + ks + (lane >> 4) * 8) * 2;
                ldsm_x4(ra[mi][0], ra[mi][1], ra[mi][2], ra[mi][3], addr);
            }
#pragma unroll
            for (int g = 0; g < 2; g++) {
                uint32_t addr = bB +
                    ((ks + (lane & 15)) * LDB2 + wn + g * 16 + (lane >> 4) * 8) * 2;
                ldsm_x4_t(rb[g][0], rb[g][1], rb[g][2], rb[g][3], addr);
            }
#pragma unroll
            for (int mi = 0; mi < 4; mi++)
#pragma unroll
                for (int ni = 0; ni < 4; ni++)
                    mma_f16(acc[mi][ni], ra[mi],
                            rb[ni >> 1][(ni & 1) * 2], rb[ni >> 1][(ni & 1) * 2 + 1]);
        }
    }

#pragma unroll
    for (int mi = 0; mi < 4; mi++)
#pragma unroll
        for (int ni = 0; ni < 4; ni++) {
            int r = rowBase + wm + mi * 16 + (lane >> 2);
            int cc = colBase + wn + ni * 8 + (lane & 3) * 2;
            if constexpr (sizeof(OutT) == 4) {
                *(float2*)&C[(size_t)r * N + cc] =
                    make_float2(acc[mi][ni][0], acc[mi][ni][1]);
                *(float2*)&C[(size_t)(r + 8) * N + cc] =
                    make_float2(acc[mi][ni][2], acc[mi][ni][3]);
            } else {
                *(__half2*)&C[(size_t)r * N + cc] =
                    __floats2half2_rn(acc[mi][ni][0], acc[mi][ni][1]);
                *(__half2*)&C[(size_t)(r + 8) * N + cc] =
                    __floats2half2_rn(acc[mi][ni][2], acc[mi][ni][3]);
            }
        }
}

// ---------------------------------------------------------------------------
// Fused prep: RoPE + scale + head-major relayout, fp16 in / fp16 out.
// qkv layout: [M, 3072] = [q(2048) | k(512) | v(512)]
// ---------------------------------------------------------------------------
__global__ void prep_kernel(const __half* __restrict__ qkv,
                            const float* __restrict__ cosb,
                            const float* __restrict__ sinb,
                            __half* __restrict__ qs,
                            __half* __restrict__ ks,
                            __half* __restrict__ vs) {
    const int NQ = Bb * Tt * Hh * 64;
    const int NK = Bb * Tt * KVH * 64;
    const int NV = Bb * Tt * KVH * 128;
    const float scale = 0.08838834764831845f;
    int idx = blockIdx.x * blockDim.x + threadIdx.x;
    if (idx < NQ) {
        int d = idx & 63;
        int h = (idx >> 6) & 15;
        int t = (idx >> 10) & 1023;
        int b = idx >> 20;
        float c = cosb[t * 64 + d];
        float s = sinb[t * 64 + d];
        size_t src = (size_t)(b * Tt + t) * NQKV + h * HD;
        float u1 = __half2float(qkv[src + d]);
        float u2 = __half2float(qkv[src + 64 + d]);
        size_t dst = ((size_t)(b * Hh + h) * Tt + t) * HD;
        qs[dst + d]      = __float2half((u1 * c - u2 * s) * scale);
        qs[dst + 64 + d] = __float2half((u1 * s + u2 * c) * scale);
    } else if (idx < NQ + NK) {
        int j = idx - NQ;
        int d = j & 63;
        int kvh = (j >> 6) & 3;
        int t = (j >> 8) & 1023;
        int b = j >> 18;
        float c = cosb[t * 64 + d];
        float s = sinb[t * 64 + d];
        size_t src = (size_t)(b * Tt + t) * NQKV + DIM + kvh * HD;
        float u1 = __half2float(qkv[src + d]);
        float u2 = __half2float(qkv[src + 64 + d]);
        size_t dst = ((size_t)(b * KVH + kvh) * Tt + t) * HD;
        ks[dst + d]      = __float2half(u1 * c - u2 * s);
        ks[dst + 64 + d] = __float2half(u1 * s + u2 * c);
    } else if (idx < NQ + NK + NV) {
        int j = idx - NQ - NK;
        int d = j & 127;
        int kvh = (j >> 7) & 3;
        int t = (j >> 9) & 1023;
        int b = j >> 19;
        size_t src = (size_t)(b * Tt + t) * NQKV + DIM + KVH * HD + kvh * HD + d;
        size_t dst = ((size_t)(b * KVH + kvh) * Tt + t) * HD;
        vs[dst + d] = qkv[src];
    }
}

// ---------------------------------------------------------------------------
// Tensor-core flash attention, plain fp16, cp.async double-buffered K/V.
// CTA: 64 q rows of one (b,h). 128 threads = 4 warps.
// ---------------------------------------------------------------------------
#define LDH2 136                      // halfs per row (128 + 8 pad)
#define F2_TILE (64 * LDH2 * 2)       // bytes per 64-row tile
#define FLASH_SMEM (5 * F2_TILE)      // Q + 2xK + 2xV  (~87 KB)

__global__ __launch_bounds__(128) void flash_tc(const __half* __restrict__ qs,
                                                const __half* __restrict__ ks,
                                                const __half* __restrict__ vs,
                                                __half* __restrict__ ctxs) {
    extern __shared__ __half fsm[];

    const int qtile = blockIdx.x;
    const int h     = blockIdx.y;
    const int b     = blockIdx.z;
    const int kvh   = h >> 2;
    const int qbase = qtile * 64;

    const int tid  = threadIdx.x;
    const int lane = tid & 31;
    const int w    = tid >> 5;
    const int gid  = lane >> 2;
    const int tig  = lane & 3;

    const uint32_t QsA = (uint32_t)__cvta_generic_to_shared(fsm);
    const uint32_t KsA = QsA + F2_TILE;
    const uint32_t VsA = KsA + 2 * F2_TILE;

    {
        const __half* qsrc = qs + ((size_t)(b * Hh + h) * Tt + qbase) * HD;
#pragma unroll
        for (int i = 0; i < 8; i++) {
            int c = tid + i * 128;
            int r = c >> 4, cc = (c & 15) * 8;
            CP_ASYNC16(QsA + (r * LDH2 + cc) * 2, qsrc + r * HD + cc);
        }
        CP_COMMIT();
    }

    auto load_kv = [&](int kt, int s) {
        const __half* kb = ks + ((size_t)(b * KVH + kvh) * Tt + kt * 64) * HD;
        const __half* vb = vs + ((size_t)(b * KVH + kvh) * Tt + kt * 64) * HD;
        const uint32_t kd = KsA + s * F2_TILE;
        const uint32_t vd = VsA + s * F2_TILE;
#pragma unroll
        for (int i = 0; i < 8; i++) {
            int c = tid + i * 128;
            int r = c >> 4, cc = (c & 15) * 8;
            CP_ASYNC16(kd + (r * LDH2 + cc) * 2, kb + r * HD + cc);
        }
#pragma unroll
        for (int i = 0; i < 8; i++) {
            int c = tid + i * 128;
            int r = c >> 4, cc = (c & 15) * 8;
            CP_ASYNC16(vd + (r * LDH2 + cc) * 2, vb + r * HD + cc);
        }
        CP_COMMIT();
    };

    load_kv(0, 0);

    float oacc[16][4];
#pragma unroll
    for (int t = 0; t < 16; t++)
#pragma unroll
        for (int r = 0; r < 4; r++) oacc[t][r] = 0.0f;
    float m0 = -INFINITY, m1 = -INFINITY, l0 = 0.0f, l1 = 0.0f;

    for (int kt = 0; kt <= qtile; ++kt) {
        if (kt < qtile) load_kv(kt + 1, (kt + 1) & 1);
        else CP_COMMIT();
        cp_wait<1>();
        __syncthreads();

        const uint32_t kB = KsA + (kt & 1) * F2_TILE;
        const uint32_t vB = VsA + (kt & 1) * F2_TILE;

        float sacc[8][4];
#pragma unroll
        for (int t = 0; t < 8; t++)
#pragma unroll
            for (int r = 0; r < 4; r++) sacc[t][r] = 0.0f;

#pragma unroll
        for (int kc = 0; kc < 8; kc++) {
            uint32_t qf[4];
            uint32_t aaddr = QsA +
                ((w * 16 + (lane & 15)) * LDH2 + kc * 16 + (lane >> 4) * 8) * 2;
            ldsm_x4(qf[0], qf[1], qf[2], qf[3], aaddr);
#pragma unroll
            for (int g = 0; g < 4; g++) {
                uint32_t kf[4];
                uint32_t baddr = kB +
                    ((g * 16 + (lane & 15)) * LDH2 + kc * 16 + (lane >> 4) * 8) * 2;
                ldsm_x4(kf[0], kf[1], kf[2], kf[3], baddr);
                mma_f16(sacc[2 * g],     qf, kf[0], kf[2]);
                mma_f16(sacc[2 * g + 1], qf, kf[1], kf[3]);
            }
        }

        if (kt == qtile) {
            int row0 = w * 16 + gid;
#pragma unroll
            for (int s8 = 0; s8 < 8; s8++) {
                int cb = s8 * 8 + tig * 2;
                if (cb     > row0)     sacc[s8][0] = -INFINITY;
                if (cb + 1 > row0)     sacc[s8][1] = -INFINITY;
                if (cb     > row0 + 8) sacc[s8][2] = -INFINITY;
                if (cb + 1 > row0 + 8) sacc[s8][3] = -INFINITY;
            }
        }

        float mx0 = -INFINITY, mx1 = -INFINITY;
#pragma unroll
        for (int s8 = 0; s8 < 8; s8++) {
            mx0 = fmaxf(mx0, fmaxf(sacc[s8][0], sacc[s8][1]));
            mx1 = fmaxf(mx1, fmaxf(sacc[s8][2], sacc[s8][3]));
        }
#pragma unroll
        for (int o = 1; o < 4; o <<= 1) {
            mx0 = fmaxf(mx0, __shfl_xor_sync(0xffffffffu, mx0, o));
            mx1 = fmaxf(mx1, __shfl_xor_sync(0xffffffffu, mx1, o));
        }
        float mn0 = fmaxf(m0, mx0), mn1 = fmaxf(m1, mx1);
        float f0 = __expf(m0 - mn0), f1 = __expf(m1 - mn1);
        float rs0 = 0.0f, rs1 = 0.0f;
#pragma unroll
        for (int s8 = 0; s8 < 8; s8++) {
            sacc[s8][0] = __expf(sacc[s8][0] - mn0);
            sacc[s8][1] = __expf(sacc[s8][1] - mn0);
            sacc[s8][2] = __expf(sacc[s8][2] - mn1);
            sacc[s8][3] = __expf(sacc[s8][3] - mn1);
            rs0 += sacc[s8][0] + sacc[s8][1];
            rs1 += sacc[s8][2] + sacc[s8][3];
        }
#pragma unroll
        for (int o = 1; o < 4; o <<= 1) {
            rs0 += __shfl_xor_sync(0xffffffffu, rs0, o);
            rs1 += __shfl_xor_sync(0xffffffffu, rs1, o);
        }
        l0 = l0 * f0 + rs0; m0 = mn0;
        l1 = l1 * f1 + rs1; m1 = mn1;
#pragma unroll
        for (int t = 0; t < 16; t++) {
            oacc[t][0] *= f0; oacc[t][1] *= f0;
            oacc[t][2] *= f1; oacc[t][3] *= f1;
        }

        uint32_t aP[4][4];
#pragma unroll
        for (int j = 0; j < 4; j++) {
#pragma unroll
            for (int half = 0; half < 2; half++) {
                int t = 2 * j + half;
                __half2 p01 = __floats2half2_rn(sacc[t][0], sacc[t][1]);
                __half2 p23 = __floats2half2_rn(sacc[t][2], sacc[t][3]);
                aP[j][2 * half]     = *(uint32_t*)&p01;
                aP[j][2 * half + 1] = *(uint32_t*)&p23;
            }
        }

#pragma unroll
        for (int j = 0; j < 4; j++) {
#pragma unroll
            for (int g = 0; g < 8; g++) {
                uint32_t vf[4];
                uint32_t baddr = vB +
                    ((j * 16 + (lane & 15)) * LDH2 + g * 16 + (lane >> 4) * 8) * 2;
                ldsm_x4_t(vf[0], vf[1], vf[2], vf[3], baddr);
                mma_f16(oacc[2 * g],     aP[j], vf[0], vf[1]);
                mma_f16(oacc[2 * g + 1], aP[j], vf[2], vf[3]);
            }
        }
        __syncthreads();
    }

    float inv0 = 1.0f / l0, inv1 = 1.0f / l1;
    int r0g = qbase + w * 16 + gid;
    size_t m0r = (size_t)(b * Tt + r0g) * DIM;
    size_t m1r = (size_t)(b * Tt + r0g + 8) * DIM;
#pragma unroll
    for (int t = 0; t < 16; t++) {
        int col = h * HD + t * 8 + tig * 2;
        *(__half2*)&ctxs[m0r + col] =
            __floats2half2_rn(oacc[t][0] * inv0, oacc[t][1] * inv0);
        *(__half2*)&ctxs[m1r + col] =
            __floats2half2_rn(oacc[t][2] * inv1, oacc[t][3] * inv1);
    }
}

// ---------------------------------------------------------------------------
// Launch
// ---------------------------------------------------------------------------
extern "C" void kernel_launch(void* const* d_in, const int* in_sizes, int n_in,
                              void* d_out, int out_size) {
    const float* x    = (const float*)d_in[0];
    const float* Wq   = (const float*)d_in[1];
    const float* Wkv  = (const float*)d_in[2];
    const float* Wo   = (const float*)d_in[3];
    const float* cosb = (const float*)d_in[4];
    const float* sinb = (const float*)d_in[5];
    float* out = (float*)d_out;

    __half *xs, *ctxs, *qkv16, *wqkv, *wos, *qsb, *ksb, *vsb;
    cudaGetSymbolAddress((void**)&xs,     g_xs);
    cudaGetSymbolAddress((void**)&ctxs,   g_ctxs);
    cudaGetSymbolAddress((void**)&qkv16,  g_qkv16);
    cudaGetSymbolAddress((void**)&wqkv,   g_wqkv);
    cudaGetSymbolAddress((void**)&wos,    g_wos);
    cudaGetSymbolAddress((void**)&qsb,    g_qs16);
    cudaGetSymbolAddress((void**)&ksb,    g_ks16);
    cudaGetSymbolAddress((void**)&vsb,    g_vs16);

    cudaFuncSetAttribute(hgemm128<__half>, cudaFuncAttributeMaxDynamicSharedMemorySize,
                         GEMM_SMEM);
    cudaFuncSetAttribute(hgemm128<float>, cudaFuncAttributeMaxDynamicSharedMemorySize,
                         GEMM_SMEM);
    cudaFuncSetAttribute(flash_tc, cudaFuncAttributeMaxDynamicSharedMemorySize,
                         FLASH_SMEM);

    const int M = MROWS;  // 4096

    // Conversions
    conv_h<<<(M * DIM / 4 + 255) / 256, 256>>>(x, xs, M * DIM);
    conv_wqkv<<<(DIM * NQKV / 4 + 255) / 256, 256>>>(Wq, Wkv, wqkv);
    conv_h<<<(DIM * DIM / 4 + 255) / 256, 256>>>(Wo, wos, DIM * DIM);

    // [q | kv] = x @ [Wq | Wkv]  (one merged GEMM, fp16 out)
    hgemm128<__half><<<dim3(NQKV / 128, M / 128), 256, GEMM_SMEM>>>(
        xs, wqkv, qkv16, M, NQKV, DIM);

    // fused rope + fp16 relayout
    {
        int total = Bb * Tt * Hh * 64 + Bb * Tt * KVH * 64 + Bb * Tt * KVH * 128;
        prep_kernel<<<(total + 255) / 256, 256>>>(qkv16, cosb, sinb, qsb, ksb, vsb);
    }

    // attention (fp16 single-term) -> fp16 ctx
    flash_tc<<<dim3(Tt / 64, Hh, Bb), 128, FLASH_SMEM>>>(qsb, ksb, vsb, ctxs);

    // out = ctx @ Wo (fp32 out)
    hgemm128<float><<<dim3(DIM / 128, M / 128), 256, GEMM_SMEM>>>(
        ctxs, wos, out, M, DIM, DIM);
}